// round 2
// baseline (speedup 1.0000x reference)
#include <cuda_runtime.h>
#include <cstdint>
#include <cstddef>

typedef unsigned long long ull;

// Problem constants
#define BB 64
#define SS 1024
#define II 256
#define HH 256

// Scratch: X gate pre-activations [S][B][4*H] fp32, biases included. 256MB.
__device__ float g_X[(size_t)SS * BB * 4 * HH];

// ---------------- f32x2 helpers (PTX-only dual-FMA path) ----------------
__device__ __forceinline__ ull pk2(float a, float b) {
    ull r; asm("mov.b64 %0, {%1, %2};" : "=l"(r) : "f"(a), "f"(b)); return r;
}
__device__ __forceinline__ void upk2(ull v, float& a, float& b) {
    asm("mov.b64 {%0, %1}, %2;" : "=f"(a), "=f"(b) : "l"(v));
}
__device__ __forceinline__ ull fma2(ull a, ull b, ull c) {
    ull d; asm("fma.rn.f32x2 %0, %1, %2, %3;" : "=l"(d) : "l"(a), "l"(b), "l"(c)); return d;
}

// Accurate fast activations (ex2/rcp approx: ~2^-22 rel err, >> 1e-3 budget)
__device__ __forceinline__ float fast_sigmoid(float x) {
    float e; asm("ex2.approx.f32 %0, %1;" : "=f"(e) : "f"(-x * 1.4426950408889634f));
    float r; asm("rcp.approx.f32 %0, %1;" : "=f"(r) : "f"(1.0f + e));
    return r;
}
__device__ __forceinline__ float fast_tanh(float x) {
    x = fminf(15.0f, fmaxf(-15.0f, x));
    float e; asm("ex2.approx.f32 %0, %1;" : "=f"(e) : "f"(x * 2.8853900817779268f)); // e^{2x}
    float r; asm("rcp.approx.f32 %0, %1;" : "=f"(r) : "f"(e + 1.0f));
    return fmaf(-2.0f, r, 1.0f);
}

// =====================================================================
// Phase 1: X[s][b][g*256+u] = inputs[b][s] . w_ig[u] + b_i[g][u] + b_h[g][u]
// GEMM [65536,256] x [256,1024], BM=BN=128, BK=32, 256 thr, 8x8 tile, f32x2
// =====================================================================
__global__ __launch_bounds__(256, 1) void lstm_xproj(
    const float* __restrict__ A,
    const float* __restrict__ wi, const float* __restrict__ wf,
    const float* __restrict__ wg, const float* __restrict__ wo,
    const float* __restrict__ bii, const float* __restrict__ bif_,
    const float* __restrict__ big_, const float* __restrict__ bio,
    const float* __restrict__ bhi, const float* __restrict__ bhf,
    const float* __restrict__ bhg, const float* __restrict__ bho)
{
    __shared__ float As[32][132];
    __shared__ float Bs[32][132];

    const int tid = threadIdx.x;
    const int m0 = blockIdx.y << 7;           // row tile (65536 / 128 = 512)
    const int n0 = blockIdx.x << 7;           // col tile (1024 / 128 = 8)
    const int g  = n0 >> 8;                   // gate id 0..3
    const int u0 = n0 & 255;

    const float* W  = (g == 0) ? wi  : (g == 1) ? wf  : (g == 2) ? wg  : wo;
    const float* bi = (g == 0) ? bii : (g == 1) ? bif_: (g == 2) ? big_: bio;
    const float* bh = (g == 0) ? bhi : (g == 1) ? bhf : (g == 2) ? bhg : bho;

    const int tx = tid & 15, ty = tid >> 4;
    const int mt = ty << 3, nt = tx << 3;
    const int lr = tid >> 3, lc = tid & 7;

    ull acc[8][4];
#pragma unroll
    for (int i = 0; i < 8; i++)
#pragma unroll
        for (int jp = 0; jp < 4; jp++) acc[i][jp] = 0ull;

    for (int kt = 0; kt < 256; kt += 32) {
#pragma unroll
        for (int it = 0; it < 4; it++) {
            int row = lr + (it << 5);
            float4 v = *(const float4*)(A + (size_t)(m0 + row) * 256 + kt + (lc << 2));
            As[(lc << 2) + 0][row] = v.x; As[(lc << 2) + 1][row] = v.y;
            As[(lc << 2) + 2][row] = v.z; As[(lc << 2) + 3][row] = v.w;
            float4 w = *(const float4*)(W + (size_t)(u0 + row) * 256 + kt + (lc << 2));
            Bs[(lc << 2) + 0][row] = w.x; Bs[(lc << 2) + 1][row] = w.y;
            Bs[(lc << 2) + 2][row] = w.z; Bs[(lc << 2) + 3][row] = w.w;
        }
        __syncthreads();
#pragma unroll
        for (int k = 0; k < 32; k++) {
            float4 a0 = *(const float4*)&As[k][mt];
            float4 a1 = *(const float4*)&As[k][mt + 4];
            ulonglong2 bq0 = *(const ulonglong2*)&Bs[k][nt];
            ulonglong2 bq1 = *(const ulonglong2*)&Bs[k][nt + 4];
            float av[8] = {a0.x, a0.y, a0.z, a0.w, a1.x, a1.y, a1.z, a1.w};
#pragma unroll
            for (int i = 0; i < 8; i++) {
                ull aa = pk2(av[i], av[i]);
                acc[i][0] = fma2(aa, bq0.x, acc[i][0]);
                acc[i][1] = fma2(aa, bq0.y, acc[i][1]);
                acc[i][2] = fma2(aa, bq1.x, acc[i][2]);
                acc[i][3] = fma2(aa, bq1.y, acc[i][3]);
            }
        }
        __syncthreads();
    }

    float bias[8];
#pragma unroll
    for (int c = 0; c < 8; c++) { int u = u0 + nt + c; bias[c] = bi[u] + bh[u]; }

#pragma unroll
    for (int i = 0; i < 8; i++) {
        int m = m0 + mt + i;
        int b = m >> 10, s = m & 1023;
        float* orow = g_X + (size_t)((s << 6) + b) * 1024 + n0 + nt;
#pragma unroll
        for (int jp = 0; jp < 4; jp++) {
            float lo, hi; upk2(acc[i][jp], lo, hi);
            float2 v = make_float2(lo + bias[jp * 2], hi + bias[jp * 2 + 1]);
            *(float2*)(orow + jp * 2) = v;
        }
    }
}

// =====================================================================
// Phase 2: sequential scan. 16 clusters x 8 CTAs. Each cluster owns 4
// batches; each CTA owns 32 hidden units (x4 gates = 128 weight rows,
// resident in SMEM). Per step: k-split f32x2 GEMM, gate math, DSMEM
// broadcast of new h, one cluster barrier. c stays in registers.
// =====================================================================
// SMEM float layout:
//   Wsm  [128][258]         at 0      (33024 floats)
//   Hsm  [2][4][256]        at 33024  (2048 floats)   h double buffer [p][b][k]
//   Red  [128][4]           at 35072  (512 floats)    per-row gate preacts
#define SM_OFF_H 33024
#define SM_OFF_R 35072
#define SM_FLOATS 35584

__global__ void __cluster_dims__(8, 1, 1) __launch_bounds__(256, 1)
lstm_scan(const float* __restrict__ h0, const float* __restrict__ c0,
          const float* __restrict__ whi, const float* __restrict__ whf,
          const float* __restrict__ whg, const float* __restrict__ who,
          float* __restrict__ out, int out_size)
{
    extern __shared__ float sm[];
    float* Wsm = sm;
    float* Hsm = sm + SM_OFF_H;
    float* Red = sm + SM_OFF_R;

    const int tid = threadIdx.x;
    unsigned rank; asm("mov.u32 %0, %%cluster_ctarank;" : "=r"(rank));
    const int b0 = (blockIdx.x >> 3) * 4;     // 4 batches per cluster

    // ---- load weight slice: rows j = g*32+uu, unit = rank*32+uu, transposed-free
    //      [j][k] padded stride 258; global coalesced (k = tid), STS conflict-free
#pragma unroll
    for (int g2 = 0; g2 < 4; g2++) {
        const float* w = (g2 == 0) ? whi : (g2 == 1) ? whf : (g2 == 2) ? whg : who;
        for (int uu = 0; uu < 32; uu++) {
            Wsm[((g2 << 5) + uu) * 258 + tid] =
                w[(size_t)(((int)rank << 5) + uu) * 256 + tid];
        }
    }
    // ---- h0 into buffer 0: Hsm[0][b][k]
    for (int idx = tid; idx < 1024; idx += 256) {
        int b = idx >> 8, k = idx & 255;
        Hsm[b * 256 + k] = h0[(size_t)(b0 + b) * 256 + k];
    }
    // ---- c in registers (combine threads tid<128 own (u,b))
    const int cu = tid >> 2, cb = tid & 3;
    const int ug = ((int)rank << 5) + cu;     // global unit index 0..255
    float c_reg = 0.0f;
    if (tid < 128) c_reg = c0[(size_t)(b0 + cb) * 256 + ug];
    __syncthreads();
    asm volatile("barrier.cluster.arrive.aligned;\n\tbarrier.cluster.wait.aligned;" ::: "memory");

    // GEMM role: 256 threads = 128 rows x 2 k-halves
    const int half = tid >> 7;
    const int j = tid & 127;
    const float* wrow = Wsm + j * 258 + (half << 7);

    unsigned smem_u32;
    asm("{ .reg .u64 t; cvta.to.shared.u64 t, %1; cvt.u32.u64 %0, t; }"
        : "=r"(smem_u32) : "l"(sm));

    int p = 0;
    float x0 = 0.f, x1 = 0.f, x2 = 0.f, x3 = 0.f;

    for (int t = 0; t < SS; t++) {
        // prefetch X gate preacts for combine stage (hidden under GEMM)
        if (tid < 128) {
            const float* xp = g_X + (size_t)t * 65536 + (size_t)(b0 + cb) * 1024 + ug;
            x0 = xp[0]; x1 = xp[256]; x2 = xp[512]; x3 = xp[768];
        }

        // ---- recurrent GEMM slice: row j, 4 batches, k in [half*128, +128)
        const float* hb = Hsm + p * 1024 + (half << 7);
        ull a0 = 0, a1 = 0, a2 = 0, a3 = 0;
#pragma unroll 16
        for (int k = 0; k < 128; k += 2) {
            ull w2  = *(const ull*)(wrow + k);
            ull hq0 = *(const ull*)(hb + 0 * 256 + k);
            ull hq1 = *(const ull*)(hb + 1 * 256 + k);
            ull hq2 = *(const ull*)(hb + 2 * 256 + k);
            ull hq3 = *(const ull*)(hb + 3 * 256 + k);
            a0 = fma2(w2, hq0, a0); a1 = fma2(w2, hq1, a1);
            a2 = fma2(w2, hq2, a2); a3 = fma2(w2, hq3, a3);
        }
        float lo, hi, s0, s1, s2, s3;
        upk2(a0, lo, hi); s0 = lo + hi;
        upk2(a1, lo, hi); s1 = lo + hi;
        upk2(a2, lo, hi); s2 = lo + hi;
        upk2(a3, lo, hi); s3 = lo + hi;

        if (half) {
            Red[j * 4 + 0] = s0; Red[j * 4 + 1] = s1;
            Red[j * 4 + 2] = s2; Red[j * 4 + 3] = s3;
        }
        __syncthreads();
        if (!half) {
            Red[j * 4 + 0] += s0; Red[j * 4 + 1] += s1;
            Red[j * 4 + 2] += s2; Red[j * 4 + 3] += s3;
        }
        __syncthreads();

        // ---- gates + state update + DSMEM broadcast of new h
        if (tid < 128) {
            float pi = Red[0 * 128 + tid] + x0;
            float pf = Red[1 * 128 + tid] + x1;
            float pg = Red[2 * 128 + tid] + x2;
            float po = Red[3 * 128 + tid] + x3;
            float gi = fast_sigmoid(pi);
            float gf = fast_sigmoid(pf);
            float gg = fast_tanh(pg);
            float go = fast_sigmoid(po);
            c_reg = gf * c_reg + gi * gg;
            float h = go * fast_tanh(c_reg);

            out[((size_t)(b0 + cb) * 1024 + t) * 256 + ug] = h;
            if (t == SS - 1) {
                size_t base = (size_t)BB * SS * HH;
                if (out_size >= (int)(base + 2u * BB * HH)) {
                    out[base + (size_t)(b0 + cb) * 256 + ug] = h;
                    out[base + (size_t)BB * HH + (size_t)(b0 + cb) * 256 + ug] = c_reg;
                }
            }

            unsigned dst = smem_u32 +
                ((unsigned)(SM_OFF_H + ((p ^ 1) << 10) + cb * 256 + ug) << 2);
#pragma unroll
            for (int rr = 0; rr < 8; rr++) {
                unsigned rem;
                asm volatile("mapa.shared::cluster.u32 %0, %1, %2;"
                             : "=r"(rem) : "r"(dst), "r"(rr));
                asm volatile("st.shared::cluster.f32 [%0], %1;"
                             :: "r"(rem), "f"(h) : "memory");
            }
        }

        asm volatile("barrier.cluster.arrive.aligned;" ::: "memory");
        asm volatile("barrier.cluster.wait.aligned;" ::: "memory");
        p ^= 1;
    }
}

// =====================================================================
extern "C" void kernel_launch(void* const* d_in, const int* in_sizes, int n_in,
                              void* d_out, int out_size)
{
    (void)in_sizes; (void)n_in;
    const float* inputs = (const float*)d_in[0];
    const float* h0     = (const float*)d_in[1];
    const float* c0     = (const float*)d_in[2];
    const float* w_ii   = (const float*)d_in[3];
    const float* w_if   = (const float*)d_in[4];
    const float* w_ig   = (const float*)d_in[5];
    const float* w_io   = (const float*)d_in[6];
    const float* b_ii   = (const float*)d_in[7];
    const float* b_if   = (const float*)d_in[8];
    const float* b_ig   = (const float*)d_in[9];
    const float* b_io   = (const float*)d_in[10];
    const float* w_hi   = (const float*)d_in[11];
    const float* w_hf   = (const float*)d_in[12];
    const float* w_hg   = (const float*)d_in[13];
    const float* w_ho   = (const float*)d_in[14];
    const float* b_hi   = (const float*)d_in[15];
    const float* b_hf   = (const float*)d_in[16];
    const float* b_hg   = (const float*)d_in[17];
    const float* b_ho   = (const float*)d_in[18];
    float* out = (float*)d_out;

    cudaFuncSetAttribute(lstm_scan, cudaFuncAttributeMaxDynamicSharedMemorySize,
                         SM_FLOATS * (int)sizeof(float));

    lstm_xproj<<<dim3(8, 512), 256>>>(inputs,
        w_ii, w_if, w_ig, w_io,
        b_ii, b_if, b_ig, b_io,
        b_hi, b_hf, b_hg, b_ho);

    lstm_scan<<<128, 256, SM_FLOATS * (int)sizeof(float)>>>(
        h0, c0, w_hi, w_hf, w_hg, w_ho, out, out_size);
}

// round 3
// speedup vs baseline: 1.2254x; 1.2254x over previous
#include <cuda_runtime.h>
#include <cstdint>
#include <cstddef>

typedef unsigned long long ull;

// Problem constants
#define BB 64
#define SS 1024
#define II 256
#define HH 256

// Scratch: X gate pre-activations [S][B][4*H] fp32, biases included. 256MB.
__device__ float g_X[(size_t)SS * BB * 4 * HH];

// ---------------- f32x2 helpers (PTX-only dual-FMA path) ----------------
__device__ __forceinline__ ull pk2(float a, float b) {
    ull r; asm("mov.b64 %0, {%1, %2};" : "=l"(r) : "f"(a), "f"(b)); return r;
}
__device__ __forceinline__ void upk2(ull v, float& a, float& b) {
    asm("mov.b64 {%0, %1}, %2;" : "=f"(a), "=f"(b) : "l"(v));
}
__device__ __forceinline__ ull fma2(ull a, ull b, ull c) {
    ull d; asm("fma.rn.f32x2 %0, %1, %2, %3;" : "=l"(d) : "l"(a), "l"(b), "l"(c)); return d;
}
__device__ __forceinline__ ull add2(ull a, ull b) {
    ull d; asm("add.rn.f32x2 %0, %1, %2;" : "=l"(d) : "l"(a), "l"(b)); return d;
}

// Accurate fast activations (ex2/rcp approx: ~2^-22 rel err, >> 1e-3 budget)
__device__ __forceinline__ float fast_sigmoid(float x) {
    float e; asm("ex2.approx.f32 %0, %1;" : "=f"(e) : "f"(-x * 1.4426950408889634f));
    float r; asm("rcp.approx.f32 %0, %1;" : "=f"(r) : "f"(1.0f + e));
    return r;
}
__device__ __forceinline__ float fast_tanh(float x) {
    x = fminf(15.0f, fmaxf(-15.0f, x));
    float e; asm("ex2.approx.f32 %0, %1;" : "=f"(e) : "f"(x * 2.8853900817779268f)); // e^{2x}
    float r; asm("rcp.approx.f32 %0, %1;" : "=f"(r) : "f"(e + 1.0f));
    return fmaf(-2.0f, r, 1.0f);
}

// =====================================================================
// Phase 1: X[s][b][g*256+u] = inputs[b][s] . w_ig[u] + b_i[g][u] + b_h[g][u]
// GEMM [65536,256] x [256,1024], BM=BN=128, BK=32, 256 thr, 8x8 tile, f32x2
// =====================================================================
__global__ __launch_bounds__(256, 2) void lstm_xproj(
    const float* __restrict__ A,
    const float* __restrict__ wi, const float* __restrict__ wf,
    const float* __restrict__ wg, const float* __restrict__ wo,
    const float* __restrict__ bii, const float* __restrict__ bif_,
    const float* __restrict__ big_, const float* __restrict__ bio,
    const float* __restrict__ bhi, const float* __restrict__ bhf,
    const float* __restrict__ bhg, const float* __restrict__ bho)
{
    __shared__ float As[32][132];
    __shared__ float Bs[32][132];

    const int tid = threadIdx.x;
    const int m0 = blockIdx.y << 7;           // row tile (65536 / 128 = 512)
    const int n0 = blockIdx.x << 7;           // col tile (1024 / 128 = 8)
    const int g  = n0 >> 8;                   // gate id 0..3
    const int u0 = n0 & 255;

    const float* W  = (g == 0) ? wi  : (g == 1) ? wf  : (g == 2) ? wg  : wo;
    const float* bi = (g == 0) ? bii : (g == 1) ? bif_: (g == 2) ? big_: bio;
    const float* bh = (g == 0) ? bhi : (g == 1) ? bhf : (g == 2) ? bhg : bho;

    const int tx = tid & 15, ty = tid >> 4;
    const int mt = ty << 3, nt = tx << 3;
    const int lr = tid >> 3, lc = tid & 7;

    ull acc[8][4];
#pragma unroll
    for (int i = 0; i < 8; i++)
#pragma unroll
        for (int jp = 0; jp < 4; jp++) acc[i][jp] = 0ull;

    for (int kt = 0; kt < 256; kt += 32) {
#pragma unroll
        for (int it = 0; it < 4; it++) {
            int row = lr + (it << 5);
            float4 v = *(const float4*)(A + (size_t)(m0 + row) * 256 + kt + (lc << 2));
            As[(lc << 2) + 0][row] = v.x; As[(lc << 2) + 1][row] = v.y;
            As[(lc << 2) + 2][row] = v.z; As[(lc << 2) + 3][row] = v.w;
            float4 w = *(const float4*)(W + (size_t)(u0 + row) * 256 + kt + (lc << 2));
            Bs[(lc << 2) + 0][row] = w.x; Bs[(lc << 2) + 1][row] = w.y;
            Bs[(lc << 2) + 2][row] = w.z; Bs[(lc << 2) + 3][row] = w.w;
        }
        __syncthreads();
#pragma unroll
        for (int k = 0; k < 32; k++) {
            float4 a0 = *(const float4*)&As[k][mt];
            float4 a1 = *(const float4*)&As[k][mt + 4];
            ulonglong2 bq0 = *(const ulonglong2*)&Bs[k][nt];
            ulonglong2 bq1 = *(const ulonglong2*)&Bs[k][nt + 4];
            float av[8] = {a0.x, a0.y, a0.z, a0.w, a1.x, a1.y, a1.z, a1.w};
#pragma unroll
            for (int i = 0; i < 8; i++) {
                ull aa = pk2(av[i], av[i]);
                acc[i][0] = fma2(aa, bq0.x, acc[i][0]);
                acc[i][1] = fma2(aa, bq0.y, acc[i][1]);
                acc[i][2] = fma2(aa, bq1.x, acc[i][2]);
                acc[i][3] = fma2(aa, bq1.y, acc[i][3]);
            }
        }
        __syncthreads();
    }

    float bias[8];
#pragma unroll
    for (int c = 0; c < 8; c++) { int u = u0 + nt + c; bias[c] = bi[u] + bh[u]; }

#pragma unroll
    for (int i = 0; i < 8; i++) {
        int m = m0 + mt + i;
        int b = m >> 10, s = m & 1023;
        float* orow = g_X + (size_t)((s << 6) + b) * 1024 + n0 + nt;
#pragma unroll
        for (int jp = 0; jp < 4; jp++) {
            float lo, hi; upk2(acc[i][jp], lo, hi);
            float2 v = make_float2(lo + bias[jp * 2], hi + bias[jp * 2 + 1]);
            *(float2*)(orow + jp * 2) = v;
        }
    }
}

// =====================================================================
// Phase 2: sequential scan. 16 clusters x 8 CTAs. Each cluster owns 4
// batches; each CTA owns 32 hidden units (x4 gates = 128 weight rows).
// Weights live in REGISTERS (64 ull per thread). h double-buffered in
// SMEM; the GEMM reads h purely via warp-broadcast LDS.128 (conflict-
// free N=1 wavefronts). 2-way k-split reduced through SMEM. New h is
// pushed to all 8 CTAs via st.shared::cluster.b64; one cluster barrier
// per step. c stays in registers.
// =====================================================================
// SMEM float layout (static, 10 KB):
//   Hsm [2][4][256]  at 0     (2048 floats)  h double buffer [p][b][k]
//   Red [128][4]     at 2048  (512 floats)   per-row gate partials/sums
#define SM_OFF_R 2048
#define SM_FLOATS 2560

__global__ void __cluster_dims__(8, 1, 1) __launch_bounds__(256, 1)
lstm_scan(const float* __restrict__ h0, const float* __restrict__ c0,
          const float* __restrict__ whi, const float* __restrict__ whf,
          const float* __restrict__ whg, const float* __restrict__ who,
          float* __restrict__ out, int out_size)
{
    __shared__ float sm[SM_FLOATS];
    float* Hsm = sm;
    float* Red = sm + SM_OFF_R;

    const int tid = threadIdx.x;
    unsigned rank; asm("mov.u32 %0, %%cluster_ctarank;" : "=r"(rank));
    const int b0 = (blockIdx.x >> 3) * 4;     // 4 batches per cluster

    // GEMM role: 256 threads = 128 rows x 2 k-halves
    const int half = tid >> 7;                // k-half: warps 0-3 -> 0, 4-7 -> 1
    const int j = tid & 127;                  // row = g*32 + uu (lane = row-in-warp)
    const int g = j >> 5, uu = j & 31;

    const float* W = (g == 0) ? whi : (g == 1) ? whf : (g == 2) ? whg : who;

    // ---- weight slice into registers: row (rank*32+uu), k in [half*128, +128)
    ull w2[64];
    {
        const ulonglong2* wp = (const ulonglong2*)(
            W + (size_t)(((int)rank << 5) + uu) * 256 + (half << 7));
#pragma unroll
        for (int c = 0; c < 32; c++) {
            ulonglong2 wq = wp[c];
            w2[2 * c]     = wq.x;
            w2[2 * c + 1] = wq.y;
        }
    }

    // ---- h0 into buffer 0: Hsm[0][b][k]
    for (int idx = tid; idx < 1024; idx += 256) {
        int b = idx >> 8, k = idx & 255;
        Hsm[b * 256 + k] = h0[(size_t)(b0 + b) * 256 + k];
    }
    // ---- c in registers (combine threads tid<128 own (unit cu, batch cb))
    const int cu = tid >> 2, cb = tid & 3;
    const int ug = ((int)rank << 5) + cu;     // global unit index 0..255
    float c_reg = 0.0f;
    if (tid < 128) c_reg = c0[(size_t)(b0 + cb) * 256 + ug];
    __syncthreads();
    asm volatile("barrier.cluster.arrive.aligned;\n\tbarrier.cluster.wait.aligned;" ::: "memory");

    unsigned smem_u32;
    asm("{ .reg .u64 t; cvta.to.shared.u64 t, %1; cvt.u32.u64 %0, t; }"
        : "=r"(smem_u32) : "l"(sm));

    int p = 0;
    float x0 = 0.f, x1 = 0.f, x2 = 0.f, x3 = 0.f;

    for (int t = 0; t < SS; t++) {
        // prefetch X gate preacts for combine stage (hidden under GEMM)
        if (tid < 128) {
            const float* xp = g_X + (size_t)t * 65536 + (size_t)(b0 + cb) * 1024 + ug;
            x0 = xp[0]; x1 = xp[256]; x2 = xp[512]; x3 = xp[768];
        }

        // ---- recurrent GEMM slice: weights from regs, h via LDS.128 broadcast
        const ulonglong2* hb = (const ulonglong2*)(Hsm + (p << 10) + (half << 7));
        ull aA0 = 0, aA1 = 0, aA2 = 0, aA3 = 0;
        ull aB0 = 0, aB1 = 0, aB2 = 0, aB3 = 0;
#pragma unroll
        for (int c = 0; c < 32; c++) {
            ulonglong2 hq0 = hb[0 * 64 + c];   // batch 0, 4 floats (broadcast)
            ulonglong2 hq1 = hb[1 * 64 + c];
            ulonglong2 hq2 = hb[2 * 64 + c];
            ulonglong2 hq3 = hb[3 * 64 + c];
            ull wlo = w2[2 * c], whi2 = w2[2 * c + 1];
            aA0 = fma2(wlo, hq0.x, aA0); aB0 = fma2(whi2, hq0.y, aB0);
            aA1 = fma2(wlo, hq1.x, aA1); aB1 = fma2(whi2, hq1.y, aB1);
            aA2 = fma2(wlo, hq2.x, aA2); aB2 = fma2(whi2, hq2.y, aB2);
            aA3 = fma2(wlo, hq3.x, aA3); aB3 = fma2(whi2, hq3.y, aB3);
        }
        float lo, hi, s0, s1, s2, s3;
        { ull v = add2(aA0, aB0); upk2(v, lo, hi); s0 = lo + hi; }
        { ull v = add2(aA1, aB1); upk2(v, lo, hi); s1 = lo + hi; }
        { ull v = add2(aA2, aB2); upk2(v, lo, hi); s2 = lo + hi; }
        { ull v = add2(aA3, aB3); upk2(v, lo, hi); s3 = lo + hi; }

        if (half) {
            *(float4*)&Red[j * 4] = make_float4(s0, s1, s2, s3);
        }
        __syncthreads();
        if (!half) {
            float4 r = *(const float4*)&Red[j * 4];
            r.x += s0; r.y += s1; r.z += s2; r.w += s3;
            *(float4*)&Red[j * 4] = r;
        }
        __syncthreads();

        // ---- gates + state update + DSMEM broadcast of new h
        if (tid < 128) {
            float pi = Red[0 * 128 + tid] + x0;
            float pf = Red[1 * 128 + tid] + x1;
            float pg = Red[2 * 128 + tid] + x2;
            float po = Red[3 * 128 + tid] + x3;
            float gi = fast_sigmoid(pi);
            float gf = fast_sigmoid(pf);
            float gg = fast_tanh(pg);
            float go = fast_sigmoid(po);
            c_reg = gf * c_reg + gi * gg;
            float h = go * fast_tanh(c_reg);

            // pair units (cu even with cu+1 = tid+4, same warp) for 64-bit stores
            float h_hi = __shfl_down_sync(0xffffffffu, h, 4);

            if ((cu & 1) == 0) {
                *(float2*)&out[((size_t)(b0 + cb) * 1024 + t) * 256 + ug] =
                    make_float2(h, h_hi);

                ull hv = pk2(h, h_hi);
                unsigned dst = smem_u32 +
                    ((unsigned)(((p ^ 1) << 10) + cb * 256 + ug) << 2);
#pragma unroll
                for (int rr = 0; rr < 8; rr++) {
                    unsigned rem;
                    asm volatile("mapa.shared::cluster.u32 %0, %1, %2;"
                                 : "=r"(rem) : "r"(dst), "r"(rr));
                    asm volatile("st.shared::cluster.b64 [%0], %1;"
                                 :: "r"(rem), "l"(hv) : "memory");
                }
            }

            if (t == SS - 1) {
                size_t base = (size_t)BB * SS * HH;
                if (out_size >= (int)(base + 2u * BB * HH)) {
                    out[base + (size_t)(b0 + cb) * 256 + ug] = h;
                    out[base + (size_t)BB * HH + (size_t)(b0 + cb) * 256 + ug] = c_reg;
                }
            }
        }

        asm volatile("barrier.cluster.arrive.aligned;" ::: "memory");
        asm volatile("barrier.cluster.wait.aligned;" ::: "memory");
        p ^= 1;
    }
}

// =====================================================================
extern "C" void kernel_launch(void* const* d_in, const int* in_sizes, int n_in,
                              void* d_out, int out_size)
{
    (void)in_sizes; (void)n_in;
    const float* inputs = (const float*)d_in[0];
    const float* h0     = (const float*)d_in[1];
    const float* c0     = (const float*)d_in[2];
    const float* w_ii   = (const float*)d_in[3];
    const float* w_if   = (const float*)d_in[4];
    const float* w_ig   = (const float*)d_in[5];
    const float* w_io   = (const float*)d_in[6];
    const float* b_ii   = (const float*)d_in[7];
    const float* b_if   = (const float*)d_in[8];
    const float* b_ig   = (const float*)d_in[9];
    const float* b_io   = (const float*)d_in[10];
    const float* w_hi   = (const float*)d_in[11];
    const float* w_hf   = (const float*)d_in[12];
    const float* w_hg   = (const float*)d_in[13];
    const float* w_ho   = (const float*)d_in[14];
    const float* b_hi   = (const float*)d_in[15];
    const float* b_hf   = (const float*)d_in[16];
    const float* b_hg   = (const float*)d_in[17];
    const float* b_ho   = (const float*)d_in[18];
    float* out = (float*)d_out;

    lstm_xproj<<<dim3(8, 512), 256>>>(inputs,
        w_ii, w_if, w_ig, w_io,
        b_ii, b_if, b_ig, b_io,
        b_hi, b_hf, b_hg, b_ho);

    lstm_scan<<<128, 256>>>(
        h0, c0, w_hi, w_hf, w_hg, w_ho, out, out_size);
}

// round 4
// speedup vs baseline: 1.3360x; 1.0903x over previous
#include <cuda_runtime.h>
#include <cstdint>
#include <cstddef>

typedef unsigned long long ull;

// Problem constants
#define BB 64
#define SS 1024
#define II 256
#define HH 256

// Scratch: X gate pre-activations [S][B][4*H] fp32, biases included. 256MB.
__device__ float g_X[(size_t)SS * BB * 4 * HH];

// ---------------- f32x2 helpers (PTX-only dual-FMA path) ----------------
__device__ __forceinline__ ull pk2(float a, float b) {
    ull r; asm("mov.b64 %0, {%1, %2};" : "=l"(r) : "f"(a), "f"(b)); return r;
}
__device__ __forceinline__ void upk2(ull v, float& a, float& b) {
    asm("mov.b64 {%0, %1}, %2;" : "=f"(a), "=f"(b) : "l"(v));
}
__device__ __forceinline__ ull fma2(ull a, ull b, ull c) {
    ull d; asm("fma.rn.f32x2 %0, %1, %2, %3;" : "=l"(d) : "l"(a), "l"(b), "l"(c)); return d;
}
__device__ __forceinline__ ull add2(ull a, ull b) {
    ull d; asm("add.rn.f32x2 %0, %1, %2;" : "=l"(d) : "l"(a), "l"(b)); return d;
}

// Accurate fast activations (ex2/rcp approx: ~2^-22 rel err, >> 1e-3 budget)
__device__ __forceinline__ float fast_sigmoid(float x) {
    float e; asm("ex2.approx.f32 %0, %1;" : "=f"(e) : "f"(-x * 1.4426950408889634f));
    float r; asm("rcp.approx.f32 %0, %1;" : "=f"(r) : "f"(1.0f + e));
    return r;
}
__device__ __forceinline__ float fast_tanh(float x) {
    x = fminf(15.0f, fmaxf(-15.0f, x));
    float e; asm("ex2.approx.f32 %0, %1;" : "=f"(e) : "f"(x * 2.8853900817779268f)); // e^{2x}
    float r; asm("rcp.approx.f32 %0, %1;" : "=f"(r) : "f"(e + 1.0f));
    return fmaf(-2.0f, r, 1.0f);
}

// =====================================================================
// Phase 1: X[s][b][g*256+u] = inputs[b][s] . w_ig[u] + b_i[g][u] + b_h[g][u]
// GEMM [65536,256] x [256,1024], BM=BN=128, BK=32, 256 thr, 8x8 tile, f32x2
// =====================================================================
__global__ __launch_bounds__(256, 2) void lstm_xproj(
    const float* __restrict__ A,
    const float* __restrict__ wi, const float* __restrict__ wf,
    const float* __restrict__ wg, const float* __restrict__ wo,
    const float* __restrict__ bii, const float* __restrict__ bif_,
    const float* __restrict__ big_, const float* __restrict__ bio,
    const float* __restrict__ bhi, const float* __restrict__ bhf,
    const float* __restrict__ bhg, const float* __restrict__ bho)
{
    __shared__ float As[32][132];
    __shared__ float Bs[32][132];

    const int tid = threadIdx.x;
    const int m0 = blockIdx.y << 7;
    const int n0 = blockIdx.x << 7;
    const int g  = n0 >> 8;
    const int u0 = n0 & 255;

    const float* W  = (g == 0) ? wi  : (g == 1) ? wf  : (g == 2) ? wg  : wo;
    const float* bi = (g == 0) ? bii : (g == 1) ? bif_: (g == 2) ? big_: bio;
    const float* bh = (g == 0) ? bhi : (g == 1) ? bhf : (g == 2) ? bhg : bho;

    const int tx = tid & 15, ty = tid >> 4;
    const int mt = ty << 3, nt = tx << 3;
    const int lr = tid >> 3, lc = tid & 7;

    ull acc[8][4];
#pragma unroll
    for (int i = 0; i < 8; i++)
#pragma unroll
        for (int jp = 0; jp < 4; jp++) acc[i][jp] = 0ull;

    for (int kt = 0; kt < 256; kt += 32) {
#pragma unroll
        for (int it = 0; it < 4; it++) {
            int row = lr + (it << 5);
            float4 v = *(const float4*)(A + (size_t)(m0 + row) * 256 + kt + (lc << 2));
            As[(lc << 2) + 0][row] = v.x; As[(lc << 2) + 1][row] = v.y;
            As[(lc << 2) + 2][row] = v.z; As[(lc << 2) + 3][row] = v.w;
            float4 w = *(const float4*)(W + (size_t)(u0 + row) * 256 + kt + (lc << 2));
            Bs[(lc << 2) + 0][row] = w.x; Bs[(lc << 2) + 1][row] = w.y;
            Bs[(lc << 2) + 2][row] = w.z; Bs[(lc << 2) + 3][row] = w.w;
        }
        __syncthreads();
#pragma unroll
        for (int k = 0; k < 32; k++) {
            float4 a0 = *(const float4*)&As[k][mt];
            float4 a1 = *(const float4*)&As[k][mt + 4];
            ulonglong2 bq0 = *(const ulonglong2*)&Bs[k][nt];
            ulonglong2 bq1 = *(const ulonglong2*)&Bs[k][nt + 4];
            float av[8] = {a0.x, a0.y, a0.z, a0.w, a1.x, a1.y, a1.z, a1.w};
#pragma unroll
            for (int i = 0; i < 8; i++) {
                ull aa = pk2(av[i], av[i]);
                acc[i][0] = fma2(aa, bq0.x, acc[i][0]);
                acc[i][1] = fma2(aa, bq0.y, acc[i][1]);
                acc[i][2] = fma2(aa, bq1.x, acc[i][2]);
                acc[i][3] = fma2(aa, bq1.y, acc[i][3]);
            }
        }
        __syncthreads();
    }

    float bias[8];
#pragma unroll
    for (int c = 0; c < 8; c++) { int u = u0 + nt + c; bias[c] = bi[u] + bh[u]; }

#pragma unroll
    for (int i = 0; i < 8; i++) {
        int m = m0 + mt + i;
        int b = m >> 10, s = m & 1023;
        float* orow = g_X + (size_t)((s << 6) + b) * 1024 + n0 + nt;
#pragma unroll
        for (int jp = 0; jp < 4; jp++) {
            float lo, hi; upk2(acc[i][jp], lo, hi);
            float2 v = make_float2(lo + bias[jp * 2], hi + bias[jp * 2 + 1]);
            *(float2*)(orow + jp * 2) = v;
        }
    }
}

// =====================================================================
// Phase 2: sequential scan. 16 clusters x 8 CTAs, 4 batches per cluster,
// 32 units (x4 gates = 128 weight rows) per CTA, weights in REGISTERS.
// Sync: NO barrier.cluster in the loop. Producers push new h to all 8
// peer CTAs via st.async.shared::cluster with mbarrier complete_tx;
// consumers do one arrive.expect_tx(4096) + try_wait per step. Two
// ping-pong mbarriers (even/odd step) + double-buffered Hsm make the
// 2-step pipeline race-free.
// =====================================================================
#define SM_OFF_R 2048
#define SM_FLOATS 2560

#define LSTM_STEP(T, DO_WAIT, WBAR, PHVAR, SBAR_IDX, DO_SEND, PBUF)          \
do {                                                                         \
    if (DO_WAIT) {                                                           \
        if (tid == 0)                                                        \
            asm volatile("mbarrier.arrive.expect_tx.shared.b64 _, [%0], %1;" \
                         :: "r"(WBAR), "r"(4096u) : "memory");               \
        asm volatile("{\n\t.reg .pred P1;\n\t"                               \
            "LW_%=:\n\t"                                                     \
            "mbarrier.try_wait.parity.acquire.cta.shared::cta.b64 P1, [%0], %1, 0x989680;\n\t" \
            "@P1 bra.uni LD_%=;\n\t"                                         \
            "bra.uni LW_%=;\n\t"                                             \
            "LD_%=:\n\t}"                                                    \
            :: "r"(WBAR), "r"((unsigned)(PHVAR)) : "memory");                \
        PHVAR ^= 1;                                                          \
    }                                                                        \
    if (tid < 128) {                                                         \
        const float* xp = g_X + (size_t)(T) * 65536                          \
                        + (size_t)(b0 + cb) * 1024 + ug;                     \
        x0 = xp[0]; x1 = xp[256]; x2 = xp[512]; x3 = xp[768];                \
    }                                                                        \
    {                                                                        \
        const ulonglong2* hb =                                               \
            (const ulonglong2*)(Hsm + ((PBUF) << 10) + (half << 7));         \
        ull aA0=0, aA1=0, aA2=0, aA3=0, aB0=0, aB1=0, aB2=0, aB3=0;          \
        _Pragma("unroll")                                                    \
        for (int c = 0; c < 32; c++) {                                       \
            ulonglong2 hq0 = hb[c];                                          \
            ulonglong2 hq1 = hb[64 + c];                                     \
            ulonglong2 hq2 = hb[128 + c];                                    \
            ulonglong2 hq3 = hb[192 + c];                                    \
            ull wlo = w2[2*c], whi2 = w2[2*c+1];                             \
            aA0 = fma2(wlo, hq0.x, aA0); aB0 = fma2(whi2, hq0.y, aB0);       \
            aA1 = fma2(wlo, hq1.x, aA1); aB1 = fma2(whi2, hq1.y, aB1);       \
            aA2 = fma2(wlo, hq2.x, aA2); aB2 = fma2(whi2, hq2.y, aB2);       \
            aA3 = fma2(wlo, hq3.x, aA3); aB3 = fma2(whi2, hq3.y, aB3);       \
        }                                                                    \
        float lo, hi, s0, s1, s2, s3;                                        \
        { ull v = add2(aA0,aB0); upk2(v,lo,hi); s0 = lo+hi; }                \
        { ull v = add2(aA1,aB1); upk2(v,lo,hi); s1 = lo+hi; }                \
        { ull v = add2(aA2,aB2); upk2(v,lo,hi); s2 = lo+hi; }                \
        { ull v = add2(aA3,aB3); upk2(v,lo,hi); s3 = lo+hi; }                \
        if (half) *(float4*)&Red[j*4] = make_float4(s0,s1,s2,s3);            \
        __syncthreads();                                                     \
        if (!half) {                                                         \
            float4 r = *(const float4*)&Red[j*4];                            \
            r.x += s0; r.y += s1; r.z += s2; r.w += s3;                      \
            *(float4*)&Red[j*4] = r;                                         \
        }                                                                    \
        __syncthreads();                                                     \
    }                                                                        \
    if (tid < 128) {                                                         \
        float pi = Red[0*128 + tid] + x0;                                    \
        float pf = Red[1*128 + tid] + x1;                                    \
        float pg = Red[2*128 + tid] + x2;                                    \
        float po = Red[3*128 + tid] + x3;                                    \
        float gi = fast_sigmoid(pi);                                         \
        float gf = fast_sigmoid(pf);                                         \
        float gg = fast_tanh(pg);                                            \
        float go = fast_sigmoid(po);                                         \
        c_reg = gf * c_reg + gi * gg;                                        \
        float h = go * fast_tanh(c_reg);                                     \
        float h_hi = __shfl_down_sync(0xffffffffu, h, 4);                    \
        if ((cu & 1) == 0) {                                                 \
            ull hv = pk2(h, h_hi);                                           \
            if (DO_SEND) {                                                   \
                unsigned dst = smem_u32 +                                    \
                    ((unsigned)(((1 - (PBUF)) << 10) + cb*256 + ug) << 2);   \
                unsigned mbl = mbar_base + ((SBAR_IDX) << 3);                \
                _Pragma("unroll")                                            \
                for (int rr = 0; rr < 8; rr++) {                             \
                    unsigned rdst, rmb;                                      \
                    asm volatile("mapa.shared::cluster.u32 %0, %1, %2;"      \
                                 : "=r"(rdst) : "r"(dst), "r"(rr));          \
                    asm volatile("mapa.shared::cluster.u32 %0, %1, %2;"      \
                                 : "=r"(rmb) : "r"(mbl), "r"(rr));           \
                    asm volatile(                                            \
  "st.async.weak.shared::cluster.mbarrier::complete_tx::bytes.b64 [%0], %1, [%2];" \
                                 :: "r"(rdst), "l"(hv), "r"(rmb) : "memory");\
                }                                                            \
            }                                                                \
            *(float2*)&out[((size_t)(b0 + cb) * 1024 + (T)) * 256 + ug] =    \
                make_float2(h, h_hi);                                        \
        }                                                                    \
        if ((T) == SS - 1) {                                                 \
            size_t basee = (size_t)BB * SS * HH;                             \
            if (out_size >= (int)(basee + 2u * BB * HH)) {                   \
                out[basee + (size_t)(b0 + cb) * 256 + ug] = h;               \
                out[basee + (size_t)BB*HH + (size_t)(b0 + cb)*256 + ug] = c_reg; \
            }                                                                \
        }                                                                    \
    }                                                                        \
} while (0)

__global__ void __cluster_dims__(8, 1, 1) __launch_bounds__(256, 1)
lstm_scan(const float* __restrict__ h0, const float* __restrict__ c0,
          const float* __restrict__ whi, const float* __restrict__ whf,
          const float* __restrict__ whg, const float* __restrict__ who,
          float* __restrict__ out, int out_size)
{
    __shared__ float sm[SM_FLOATS];
    __shared__ __align__(16) ull mbars[2];
    float* Hsm = sm;
    float* Red = sm + SM_OFF_R;

    const int tid = threadIdx.x;
    unsigned rank; asm("mov.u32 %0, %%cluster_ctarank;" : "=r"(rank));
    const int b0 = (blockIdx.x >> 3) * 4;

    const int half = tid >> 7;
    const int j = tid & 127;
    const int g = j >> 5, uu = j & 31;

    const float* W = (g == 0) ? whi : (g == 1) ? whf : (g == 2) ? whg : who;

    // weight slice into registers
    ull w2[64];
    {
        const ulonglong2* wp = (const ulonglong2*)(
            W + (size_t)(((int)rank << 5) + uu) * 256 + (half << 7));
#pragma unroll
        for (int c = 0; c < 32; c++) {
            ulonglong2 wq = wp[c];
            w2[2 * c]     = wq.x;
            w2[2 * c + 1] = wq.y;
        }
    }

    // h0 into buffer 0
    for (int idx = tid; idx < 1024; idx += 256) {
        int b = idx >> 8, k = idx & 255;
        Hsm[b * 256 + k] = h0[(size_t)(b0 + b) * 256 + k];
    }
    const int cu = tid >> 2, cb = tid & 3;
    const int ug = ((int)rank << 5) + cu;
    float c_reg = 0.0f;
    if (tid < 128) c_reg = c0[(size_t)(b0 + cb) * 256 + ug];

    unsigned smem_u32, mbar_base;
    asm("{ .reg .u64 t; cvta.to.shared.u64 t, %1; cvt.u32.u64 %0, t; }"
        : "=r"(smem_u32) : "l"(sm));
    asm("{ .reg .u64 t; cvta.to.shared.u64 t, %1; cvt.u32.u64 %0, t; }"
        : "=r"(mbar_base) : "l"(mbars));
    const unsigned mbar0 = mbar_base;
    const unsigned mbar1 = mbar_base + 8;

    if (tid == 0) {
        asm volatile("mbarrier.init.shared.b64 [%0], 1;" :: "r"(mbar0) : "memory");
        asm volatile("mbarrier.init.shared.b64 [%0], 1;" :: "r"(mbar1) : "memory");
    }
    __syncthreads();
    asm volatile("barrier.cluster.arrive.aligned;" ::: "memory");
    asm volatile("barrier.cluster.wait.aligned;" ::: "memory");

    int p = 0;
    int ph0 = 0, ph1 = 0;
    float x0 = 0.f, x1 = 0.f, x2 = 0.f, x3 = 0.f;

    for (int tt = 0; tt < SS; tt += 2) {
        // even step: waits mbar0 (skip at tt==0), sends into mbar1
        LSTM_STEP(tt, (tt > 0), mbar0, ph0, 1, 1, p);
        p ^= 1;
        // odd step: waits mbar1, sends into mbar0 (skip at last step)
        LSTM_STEP(tt + 1, 1, mbar1, ph1, 0, (tt + 1 < SS - 1), p);
        p ^= 1;
    }
}

// =====================================================================
extern "C" void kernel_launch(void* const* d_in, const int* in_sizes, int n_in,
                              void* d_out, int out_size)
{
    (void)in_sizes; (void)n_in;
    const float* inputs = (const float*)d_in[0];
    const float* h0     = (const float*)d_in[1];
    const float* c0     = (const float*)d_in[2];
    const float* w_ii   = (const float*)d_in[3];
    const float* w_if   = (const float*)d_in[4];
    const float* w_ig   = (const float*)d_in[5];
    const float* w_io   = (const float*)d_in[6];
    const float* b_ii   = (const float*)d_in[7];
    const float* b_if   = (const float*)d_in[8];
    const float* b_ig   = (const float*)d_in[9];
    const float* b_io   = (const float*)d_in[10];
    const float* w_hi   = (const float*)d_in[11];
    const float* w_hf   = (const float*)d_in[12];
    const float* w_hg   = (const float*)d_in[13];
    const float* w_ho   = (const float*)d_in[14];
    const float* b_hi   = (const float*)d_in[15];
    const float* b_hf   = (const float*)d_in[16];
    const float* b_hg   = (const float*)d_in[17];
    const float* b_ho   = (const float*)d_in[18];
    float* out = (float*)d_out;

    lstm_xproj<<<dim3(8, 512), 256>>>(inputs,
        w_ii, w_if, w_ig, w_io,
        b_ii, b_if, b_ig, b_io,
        b_hi, b_hf, b_hg, b_ho);

    lstm_scan<<<128, 256>>>(
        h0, c0, w_hi, w_hf, w_hg, w_ho, out, out_size);
}

// round 5
// speedup vs baseline: 1.3805x; 1.0333x over previous
#include <cuda_runtime.h>
#include <cstdint>
#include <cstddef>

typedef unsigned long long ull;

// Problem constants
#define BB 64
#define SS 1024
#define II 256
#define HH 256

// Scratch: X gate pre-activations [S][B][4*H] fp32, biases included. 256MB.
__device__ float g_X[(size_t)SS * BB * 4 * HH];

// ---------------- f32x2 helpers (PTX-only dual-FMA path) ----------------
__device__ __forceinline__ ull pk2(float a, float b) {
    ull r; asm("mov.b64 %0, {%1, %2};" : "=l"(r) : "f"(a), "f"(b)); return r;
}
__device__ __forceinline__ void upk2(ull v, float& a, float& b) {
    asm("mov.b64 {%0, %1}, %2;" : "=f"(a), "=f"(b) : "l"(v));
}
__device__ __forceinline__ ull fma2(ull a, ull b, ull c) {
    ull d; asm("fma.rn.f32x2 %0, %1, %2, %3;" : "=l"(d) : "l"(a), "l"(b), "l"(c)); return d;
}

// Accurate fast activations (ex2/rcp approx: ~2^-22 rel err, >> 1e-3 budget)
__device__ __forceinline__ float fast_sigmoid(float x) {
    float e; asm("ex2.approx.f32 %0, %1;" : "=f"(e) : "f"(-x * 1.4426950408889634f));
    float r; asm("rcp.approx.f32 %0, %1;" : "=f"(r) : "f"(1.0f + e));
    return r;
}
__device__ __forceinline__ float fast_tanh(float x) {
    x = fminf(15.0f, fmaxf(-15.0f, x));
    float e; asm("ex2.approx.f32 %0, %1;" : "=f"(e) : "f"(x * 2.8853900817779268f)); // e^{2x}
    float r; asm("rcp.approx.f32 %0, %1;" : "=f"(r) : "f"(e + 1.0f));
    return fmaf(-2.0f, r, 1.0f);
}

// =====================================================================
// Phase 1: X projection GEMM [65536,256] x [256,1024] (unchanged)
// =====================================================================
__global__ __launch_bounds__(256, 2) void lstm_xproj(
    const float* __restrict__ A,
    const float* __restrict__ wi, const float* __restrict__ wf,
    const float* __restrict__ wg, const float* __restrict__ wo,
    const float* __restrict__ bii, const float* __restrict__ bif_,
    const float* __restrict__ big_, const float* __restrict__ bio,
    const float* __restrict__ bhi, const float* __restrict__ bhf,
    const float* __restrict__ bhg, const float* __restrict__ bho)
{
    __shared__ float As[32][132];
    __shared__ float Bs[32][132];

    const int tid = threadIdx.x;
    const int m0 = blockIdx.y << 7;
    const int n0 = blockIdx.x << 7;
    const int g  = n0 >> 8;
    const int u0 = n0 & 255;

    const float* W  = (g == 0) ? wi  : (g == 1) ? wf  : (g == 2) ? wg  : wo;
    const float* bi = (g == 0) ? bii : (g == 1) ? bif_: (g == 2) ? big_: bio;
    const float* bh = (g == 0) ? bhi : (g == 1) ? bhf : (g == 2) ? bhg : bho;

    const int tx = tid & 15, ty = tid >> 4;
    const int mt = ty << 3, nt = tx << 3;
    const int lr = tid >> 3, lc = tid & 7;

    ull acc[8][4];
#pragma unroll
    for (int i = 0; i < 8; i++)
#pragma unroll
        for (int jp = 0; jp < 4; jp++) acc[i][jp] = 0ull;

    for (int kt = 0; kt < 256; kt += 32) {
#pragma unroll
        for (int it = 0; it < 4; it++) {
            int row = lr + (it << 5);
            float4 v = *(const float4*)(A + (size_t)(m0 + row) * 256 + kt + (lc << 2));
            As[(lc << 2) + 0][row] = v.x; As[(lc << 2) + 1][row] = v.y;
            As[(lc << 2) + 2][row] = v.z; As[(lc << 2) + 3][row] = v.w;
            float4 w = *(const float4*)(W + (size_t)(u0 + row) * 256 + kt + (lc << 2));
            Bs[(lc << 2) + 0][row] = w.x; Bs[(lc << 2) + 1][row] = w.y;
            Bs[(lc << 2) + 2][row] = w.z; Bs[(lc << 2) + 3][row] = w.w;
        }
        __syncthreads();
#pragma unroll
        for (int k = 0; k < 32; k++) {
            float4 a0 = *(const float4*)&As[k][mt];
            float4 a1 = *(const float4*)&As[k][mt + 4];
            ulonglong2 bq0 = *(const ulonglong2*)&Bs[k][nt];
            ulonglong2 bq1 = *(const ulonglong2*)&Bs[k][nt + 4];
            float av[8] = {a0.x, a0.y, a0.z, a0.w, a1.x, a1.y, a1.z, a1.w};
#pragma unroll
            for (int i = 0; i < 8; i++) {
                ull aa = pk2(av[i], av[i]);
                acc[i][0] = fma2(aa, bq0.x, acc[i][0]);
                acc[i][1] = fma2(aa, bq0.y, acc[i][1]);
                acc[i][2] = fma2(aa, bq1.x, acc[i][2]);
                acc[i][3] = fma2(aa, bq1.y, acc[i][3]);
            }
        }
        __syncthreads();
    }

    float bias[8];
#pragma unroll
    for (int c = 0; c < 8; c++) { int u = u0 + nt + c; bias[c] = bi[u] + bh[u]; }

#pragma unroll
    for (int i = 0; i < 8; i++) {
        int m = m0 + mt + i;
        int b = m >> 10, s = m & 1023;
        float* orow = g_X + (size_t)((s << 6) + b) * 1024 + n0 + nt;
#pragma unroll
        for (int jp = 0; jp < 4; jp++) {
            float lo, hi; upk2(acc[i][jp], lo, hi);
            float2 v = make_float2(lo + bias[jp * 2], hi + bias[jp * 2 + 1]);
            *(float2*)(orow + jp * 2) = v;
        }
    }
}

// =====================================================================
// Phase 2: sequential scan. 16 clusters x 8 CTAs, 4 batches/cluster,
// 32 units (x4 gates = 128 rows) per CTA. 512 THREADS: 4-way k-split
// (quarters of 64), weights in registers (32 ull/thread). h read via
// broadcast LDS.128. 4-partial SMEM reduction, one __syncthreads.
// Sync across CTAs: st.async + mbarrier complete_tx (ping-pong pair).
// =====================================================================
// SMEM float layout:
//   Hsm [2][4][256]   at 0     (2048 floats)  h double buffer
//   Red [4][128][4]   at 2048  (2048 floats)  k-quarter partials
#define SM_OFF_R 2048
#define SM_FLOATS 4096

#define LSTM_STEP(T, DO_WAIT, WBAR, PHVAR, SBAR_IDX, DO_SEND, PBUF)          \
do {                                                                         \
    if (DO_WAIT) {                                                           \
        if (tid == 0)                                                        \
            asm volatile("mbarrier.arrive.expect_tx.shared.b64 _, [%0], %1;" \
                         :: "r"(WBAR), "r"(4096u) : "memory");               \
        asm volatile("{\n\t.reg .pred P1;\n\t"                               \
            "LW_%=:\n\t"                                                     \
            "mbarrier.try_wait.parity.acquire.cta.shared::cta.b64 P1, [%0], %1, 0x989680;\n\t" \
            "@P1 bra.uni LD_%=;\n\t"                                         \
            "bra.uni LW_%=;\n\t"                                             \
            "LD_%=:\n\t}"                                                    \
            :: "r"(WBAR), "r"((unsigned)(PHVAR)) : "memory");                \
        PHVAR ^= 1;                                                          \
    }                                                                        \
    if (tid < 128) {                                                         \
        const float* xp = g_X + (size_t)(T) * 65536                          \
                        + (size_t)(b0 + cb) * 1024 + ug;                     \
        x0 = xp[0]; x1 = xp[256]; x2 = xp[512]; x3 = xp[768];                \
    }                                                                        \
    {                                                                        \
        const ulonglong2* hb =                                               \
            (const ulonglong2*)(Hsm + ((PBUF) << 10) + (q << 6));            \
        ull a0 = 0, a1 = 0, a2 = 0, a3 = 0;                                  \
        _Pragma("unroll")                                                    \
        for (int c = 0; c < 16; c++) {                                       \
            ulonglong2 hq0 = hb[c];                                          \
            ulonglong2 hq1 = hb[64 + c];                                     \
            ulonglong2 hq2 = hb[128 + c];                                    \
            ulonglong2 hq3 = hb[192 + c];                                    \
            ull wlo = w2[2*c], whi2 = w2[2*c+1];                             \
            a0 = fma2(whi2, hq0.y, fma2(wlo, hq0.x, a0));                    \
            a1 = fma2(whi2, hq1.y, fma2(wlo, hq1.x, a1));                    \
            a2 = fma2(whi2, hq2.y, fma2(wlo, hq2.x, a2));                    \
            a3 = fma2(whi2, hq3.y, fma2(wlo, hq3.x, a3));                    \
        }                                                                    \
        float lo, hi, s0, s1, s2, s3;                                        \
        upk2(a0, lo, hi); s0 = lo + hi;                                      \
        upk2(a1, lo, hi); s1 = lo + hi;                                      \
        upk2(a2, lo, hi); s2 = lo + hi;                                      \
        upk2(a3, lo, hi); s3 = lo + hi;                                      \
        *(float4*)&Red[(q << 9) + (j << 2)] = make_float4(s0, s1, s2, s3);   \
        __syncthreads();                                                     \
    }                                                                        \
    if (tid < 128) {                                                         \
        float pi = 0.f, pf = 0.f, pg = 0.f, po = 0.f;                        \
        _Pragma("unroll")                                                    \
        for (int qq = 0; qq < 4; qq++) {                                     \
            const float* rq = Red + (qq << 9) + cb;                          \
            pi += rq[(0*32 + cu) << 2];                                      \
            pf += rq[(1*32 + cu) << 2];                                      \
            pg += rq[(2*32 + cu) << 2];                                      \
            po += rq[(3*32 + cu) << 2];                                      \
        }                                                                    \
        pi += x0; pf += x1; pg += x2; po += x3;                              \
        float gi = fast_sigmoid(pi);                                         \
        float gf = fast_sigmoid(pf);                                         \
        float gg = fast_tanh(pg);                                            \
        float go = fast_sigmoid(po);                                         \
        c_reg = gf * c_reg + gi * gg;                                        \
        float h = go * fast_tanh(c_reg);                                     \
        float h_hi = __shfl_down_sync(0xffffffffu, h, 4);                    \
        if ((cu & 1) == 0) {                                                 \
            ull hv = pk2(h, h_hi);                                           \
            if (DO_SEND) {                                                   \
                unsigned dst = smem_u32 +                                    \
                    ((unsigned)(((1 - (PBUF)) << 10) + cb*256 + ug) << 2);   \
                unsigned mbl = mbar_base + ((SBAR_IDX) << 3);                \
                _Pragma("unroll")                                            \
                for (int rr = 0; rr < 8; rr++) {                             \
                    unsigned rdst, rmb;                                      \
                    asm volatile("mapa.shared::cluster.u32 %0, %1, %2;"      \
                                 : "=r"(rdst) : "r"(dst), "r"(rr));          \
                    asm volatile("mapa.shared::cluster.u32 %0, %1, %2;"      \
                                 : "=r"(rmb) : "r"(mbl), "r"(rr));           \
                    asm volatile(                                            \
  "st.async.weak.shared::cluster.mbarrier::complete_tx::bytes.b64 [%0], %1, [%2];" \
                                 :: "r"(rdst), "l"(hv), "r"(rmb) : "memory");\
                }                                                            \
            }                                                                \
            *(float2*)&out[((size_t)(b0 + cb) * 1024 + (T)) * 256 + ug] =    \
                make_float2(h, h_hi);                                        \
        }                                                                    \
        if ((T) == SS - 1) {                                                 \
            size_t basee = (size_t)BB * SS * HH;                             \
            if (out_size >= (int)(basee + 2u * BB * HH)) {                   \
                out[basee + (size_t)(b0 + cb) * 256 + ug] = h;               \
                out[basee + (size_t)BB*HH + (size_t)(b0 + cb)*256 + ug] = c_reg; \
            }                                                                \
        }                                                                    \
    }                                                                        \
} while (0)

__global__ void __cluster_dims__(8, 1, 1) __launch_bounds__(512, 1)
lstm_scan(const float* __restrict__ h0, const float* __restrict__ c0,
          const float* __restrict__ whi, const float* __restrict__ whf,
          const float* __restrict__ whg, const float* __restrict__ who,
          float* __restrict__ out, int out_size)
{
    __shared__ float sm[SM_FLOATS];
    __shared__ __align__(16) ull mbars[2];
    float* Hsm = sm;
    float* Red = sm + SM_OFF_R;

    const int tid = threadIdx.x;
    unsigned rank; asm("mov.u32 %0, %%cluster_ctarank;" : "=r"(rank));
    const int b0 = (blockIdx.x >> 3) * 4;

    const int q = tid >> 7;                   // k-quarter 0..3
    const int j = tid & 127;                  // row = g*32 + uu
    const int g = j >> 5, uu = j & 31;

    const float* W = (g == 0) ? whi : (g == 1) ? whf : (g == 2) ? whg : who;

    // weight slice into registers: row (rank*32+uu), k in [q*64, q*64+64)
    ull w2[32];
    {
        const ulonglong2* wp = (const ulonglong2*)(
            W + (size_t)(((int)rank << 5) + uu) * 256 + (q << 6));
#pragma unroll
        for (int c = 0; c < 16; c++) {
            ulonglong2 wq = wp[c];
            w2[2 * c]     = wq.x;
            w2[2 * c + 1] = wq.y;
        }
    }

    // h0 into buffer 0
    for (int idx = tid; idx < 1024; idx += 512) {
        int b = idx >> 8, k = idx & 255;
        Hsm[b * 256 + k] = h0[(size_t)(b0 + b) * 256 + k];
    }
    const int cu = tid >> 2, cb = tid & 3;    // tail roles (tid < 128)
    const int ug = ((int)rank << 5) + (cu & 31);
    float c_reg = 0.0f;
    if (tid < 128) c_reg = c0[(size_t)(b0 + cb) * 256 + ug];

    unsigned smem_u32, mbar_base;
    asm("{ .reg .u64 t; cvta.to.shared.u64 t, %1; cvt.u32.u64 %0, t; }"
        : "=r"(smem_u32) : "l"(sm));
    asm("{ .reg .u64 t; cvta.to.shared.u64 t, %1; cvt.u32.u64 %0, t; }"
        : "=r"(mbar_base) : "l"(mbars));
    const unsigned mbar0 = mbar_base;
    const unsigned mbar1 = mbar_base + 8;

    if (tid == 0) {
        asm volatile("mbarrier.init.shared.b64 [%0], 1;" :: "r"(mbar0) : "memory");
        asm volatile("mbarrier.init.shared.b64 [%0], 1;" :: "r"(mbar1) : "memory");
    }
    __syncthreads();
    asm volatile("barrier.cluster.arrive.aligned;" ::: "memory");
    asm volatile("barrier.cluster.wait.aligned;" ::: "memory");

    int p = 0;
    int ph0 = 0, ph1 = 0;
    float x0 = 0.f, x1 = 0.f, x2 = 0.f, x3 = 0.f;

    for (int tt = 0; tt < SS; tt += 2) {
        LSTM_STEP(tt, (tt > 0), mbar0, ph0, 1, 1, p);
        p ^= 1;
        LSTM_STEP(tt + 1, 1, mbar1, ph1, 0, (tt + 1 < SS - 1), p);
        p ^= 1;
    }
}

// =====================================================================
extern "C" void kernel_launch(void* const* d_in, const int* in_sizes, int n_in,
                              void* d_out, int out_size)
{
    (void)in_sizes; (void)n_in;
    const float* inputs = (const float*)d_in[0];
    const float* h0     = (const float*)d_in[1];
    const float* c0     = (const float*)d_in[2];
    const float* w_ii   = (const float*)d_in[3];
    const float* w_if   = (const float*)d_in[4];
    const float* w_ig   = (const float*)d_in[5];
    const float* w_io   = (const float*)d_in[6];
    const float* b_ii   = (const float*)d_in[7];
    const float* b_if   = (const float*)d_in[8];
    const float* b_ig   = (const float*)d_in[9];
    const float* b_io   = (const float*)d_in[10];
    const float* w_hi   = (const float*)d_in[11];
    const float* w_hf   = (const float*)d_in[12];
    const float* w_hg   = (const float*)d_in[13];
    const float* w_ho   = (const float*)d_in[14];
    const float* b_hi   = (const float*)d_in[15];
    const float* b_hf   = (const float*)d_in[16];
    const float* b_hg   = (const float*)d_in[17];
    const float* b_ho   = (const float*)d_in[18];
    float* out = (float*)d_out;

    lstm_xproj<<<dim3(8, 512), 256>>>(inputs,
        w_ii, w_if, w_ig, w_io,
        b_ii, b_if, b_ig, b_io,
        b_hi, b_hf, b_hg, b_ho);

    lstm_scan<<<128, 512>>>(
        h0, c0, w_hi, w_hf, w_hg, w_ho, out, out_size);
}